// round 4
// baseline (speedup 1.0000x reference)
#include <cuda_runtime.h>
#include <math.h>
#include <stdint.h>

#define BATCH  256
#define D      512
#define S      196

// device scratch (no allocs allowed)
__device__ float g_w[BATCH * D];          // w[b,d] = mem*v + ctrl*w_attn
__device__ float g_rai[4 * BATCH * 256];  // per-quarter partial logits, stride 256

// packed fp32x2 FMA (Blackwell): d = a*b + c on two lanes, full fp32 precision
__device__ __forceinline__ uint64_t fma2(uint64_t a, uint64_t b, uint64_t c) {
    uint64_t d;
    asm("fma.rn.f32x2 %0, %1, %2, %3;" : "=l"(d) : "l"(a), "l"(b), "l"(c));
    return d;
}
__device__ __forceinline__ uint64_t pack2(float lo, float hi) {
    uint64_t r;
    asm("mov.b64 %0, {%1, %2};" : "=l"(r) : "f"(lo), "f"(hi));
    return r;
}
__device__ __forceinline__ void unpack2(uint64_t v, float& lo, float& hi) {
    asm("mov.b64 {%0, %1}, %2;" : "=f"(lo), "=f"(hi) : "l"(v));
}

// ---------------------------------------------------------------------------
// Prep: w[b,d] = memory[b,d]*(sum_e u[b,e]*W[e,d]) + ctrl[b,d]*w_attn[d],
//       u[b,e] = ctrl[b,e]*w_attn[e].
// Grid (4 d-tiles, 64 b-tiles), 256 threads. CTA tile: 4 batches x 128 d.
// Thread: dg = tid&31 (4 consecutive d), kz = tid>>5 (8-way k-split, 64 e).
// Inner loop: 1 LDG.128 (W) + 4 LDS.64 (u-pairs) + 2 packs + 8 fma.f32x2.
// ---------------------------------------------------------------------------
__global__ __launch_bounds__(256) void prep_kernel(
    const float* __restrict__ memory,
    const float* __restrict__ ctrl,
    const float* __restrict__ W,       // [e, d] row-major
    const float* __restrict__ w_attn)
{
    __shared__ float sm[4096];         // phase1: u2[j][e] pairs (16KB); phase2: partials

    const int tid = threadIdx.x;
    const int dg  = tid & 31;
    const int kz  = tid >> 5;          // 0..7
    const int d0  = blockIdx.x * 128 + dg * 4;
    const int b0  = blockIdx.y * 4;

    // u2[j][e] = {u, u}, u = ctrl[b0+j, e] * w_attn[e]
    for (int idx = tid; idx < 2048; idx += 256) {
        int j = idx >> 9, e = idx & 511;
        float u = ctrl[(b0 + j) * D + e] * w_attn[e];
        sm[idx * 2]     = u;
        sm[idx * 2 + 1] = u;
    }
    __syncthreads();

    uint64_t acc[4][2];
#pragma unroll
    for (int j = 0; j < 4; j++) { acc[j][0] = 0ull; acc[j][1] = 0ull; }

    const int e0 = kz * 64;
    const float4* __restrict__ W4 = reinterpret_cast<const float4*>(W + d0);
#pragma unroll 4
    for (int e = e0; e < e0 + 64; e++) {
        float4 w4 = W4[e * (D / 4)];
        uint64_t wlo = pack2(w4.x, w4.y);
        uint64_t whi = pack2(w4.z, w4.w);
#pragma unroll
        for (int j = 0; j < 4; j++) {
            uint64_t uu = *reinterpret_cast<const uint64_t*>(&sm[(j * 512 + e) * 2]);
            acc[j][0] = fma2(wlo, uu, acc[j][0]);
            acc[j][1] = fma2(whi, uu, acc[j][1]);
        }
    }
    __syncthreads();

    // partials: sm[kz*512 + j*128 + dg*4 + i]
#pragma unroll
    for (int j = 0; j < 4; j++) {
        float x0, x1, x2, x3;
        unpack2(acc[j][0], x0, x1);
        unpack2(acc[j][1], x2, x3);
        float4 v4 = make_float4(x0, x1, x2, x3);
        *reinterpret_cast<float4*>(&sm[kz * 512 + j * 128 + dg * 4]) = v4;
    }
    __syncthreads();

#pragma unroll
    for (int o = tid; o < 512; o += 256) {
        float v = 0.f;
#pragma unroll
        for (int k = 0; k < 8; k++) v += sm[k * 512 + o];
        int j  = o >> 7;
        int dd = o & 127;
        int b  = b0 + j;
        int dgl = blockIdx.x * 128 + dd;
        g_w[b * D + dgl] = memory[b * D + dgl] * v + ctrl[b * D + dgl] * w_attn[dgl];
    }
}

// ---------------------------------------------------------------------------
// Kernel A: partial logits. Grid 1024 = (b, quarter): each CTA owns 128 d-rows.
// 256 threads / 8 warps; warp-per-row float4 loads. Streams kb from DRAM once.
// ---------------------------------------------------------------------------
__global__ __launch_bounds__(256) void logits_kernel(
    const float* __restrict__ kb)      // [B, D, S]
{
    const int q    = blockIdx.x & 3;
    const int b    = blockIdx.x >> 2;
    const int tid  = threadIdx.x;
    const int wid  = tid >> 5;
    const int lane = tid & 31;
    const int l2   = lane < 17 ? lane : 16;     // clamp second segment
    const float mB = lane < 17 ? 1.f : 0.f;

    __shared__ float w_s[128];
    __shared__ __align__(16) float part[8][200];

    const float* __restrict__ base = kb + (size_t)b * (D * S) + (size_t)q * (128 * S);

    if (tid < 128) w_s[tid] = g_w[b * D + q * 128 + tid];
    __syncthreads();

    float4 accA = make_float4(0.f, 0.f, 0.f, 0.f);
    float4 accB = make_float4(0.f, 0.f, 0.f, 0.f);

#pragma unroll 4
    for (int r = wid; r < 128; r += 8) {
        const float wv = w_s[r];
        const float4* __restrict__ row = reinterpret_cast<const float4*>(base + r * S);
        float4 va = row[lane];          // s = 4*lane..+3       (s < 128)
        float4 vb = row[32 + l2];       // s = 128+4*l2..+3     (s < 196)
        accA.x += wv * va.x;  accA.y += wv * va.y;
        accA.z += wv * va.z;  accA.w += wv * va.w;
        float wb = wv * mB;
        accB.x += wb * vb.x;  accB.y += wb * vb.y;
        accB.z += wb * vb.z;  accB.w += wb * vb.w;
    }

    *reinterpret_cast<float4*>(&part[wid][4 * lane]) = accA;
    if (lane < 17)
        *reinterpret_cast<float4*>(&part[wid][128 + 4 * lane]) = accB;
    __syncthreads();

    if (tid < S) {
        float sum = 0.f;
#pragma unroll
        for (int w = 0; w < 8; w++) sum += part[w][tid];
        g_rai[blockIdx.x * 256 + tid] = sum;
    }
}

// ---------------------------------------------------------------------------
// Kernel B: softmax (redundant per CTA, deterministic) + weighted sum.
// Grid 1024 = (b, quarter), b iterated in DESCENDING order so the re-read of
// kb chases kernel A's L2 residue from the hot end (LRU-friendly).
// ---------------------------------------------------------------------------
__global__ __launch_bounds__(256) void readout_kernel(
    const float* __restrict__ kb,      // [B, D, S]
    float* __restrict__ out)           // [B, D]
{
    const int q    = blockIdx.x & 3;
    const int b    = (BATCH - 1) - (blockIdx.x >> 2);   // descending batch order
    const int tid  = threadIdx.x;
    const int wid  = tid >> 5;
    const int lane = tid & 31;
    const int l2   = lane < 17 ? lane : 16;
    const float mB = lane < 17 ? 1.f : 0.f;

    __shared__ __align__(16) float rvi_s[208];
    __shared__ float red[8];

    // full rai = sum of 4 quarter-partials (fixed order -> deterministic)
    float rai = -INFINITY;
    if (tid < S) {
        float sum = 0.f;
#pragma unroll
        for (int k = 0; k < 4; k++) sum += g_rai[(b * 4 + k) * 256 + tid];
        rai = sum;
    }

    // ---- softmax over s ----
    float m = rai;
#pragma unroll
    for (int off = 16; off > 0; off >>= 1)
        m = fmaxf(m, __shfl_xor_sync(0xffffffff, m, off));
    if (lane == 0) red[wid] = m;
    __syncthreads();
    if (wid == 0) {
        float v = (lane < 8) ? red[lane] : -INFINITY;
#pragma unroll
        for (int off = 4; off > 0; off >>= 1)
            v = fmaxf(v, __shfl_xor_sync(0xffffffff, v, off));
        if (lane == 0) red[0] = v;
    }
    __syncthreads();
    const float gmax = red[0];
    __syncthreads();

    float p = (tid < S) ? expf(rai - gmax) : 0.f;
    float sacc = p;
#pragma unroll
    for (int off = 16; off > 0; off >>= 1)
        sacc += __shfl_xor_sync(0xffffffff, sacc, off);
    if (lane == 0) red[wid] = sacc;
    __syncthreads();
    if (wid == 0) {
        float v = (lane < 8) ? red[lane] : 0.f;
#pragma unroll
        for (int off = 4; off > 0; off >>= 1)
            v += __shfl_xor_sync(0xffffffff, v, off);
        if (lane == 0) red[0] = v;
    }
    __syncthreads();
    const float inv_sum = 1.f / red[0];
    if (tid < S) rvi_s[tid] = p * inv_sum;
    if (tid >= S && tid < 208) rvi_s[tid] = 0.f;
    __syncthreads();

    const float4 rA = *reinterpret_cast<const float4*>(&rvi_s[4 * lane]);
    const float4 rB = *reinterpret_cast<const float4*>(&rvi_s[128 + 4 * l2]);

    const float* __restrict__ base = kb + (size_t)b * (D * S);

    // out[e] = sum_s rvi[s] * kb[e][s]; 16 rows per warp
#pragma unroll 4
    for (int r = wid; r < 128; r += 8) {
        const int e = q * 128 + r;
        const float4* __restrict__ row = reinterpret_cast<const float4*>(base + e * S);
        float4 va = row[lane];
        float4 vb = row[32 + l2];
        float sum = va.x * rA.x + va.y * rA.y + va.z * rA.z + va.w * rA.w
                  + mB * (vb.x * rB.x + vb.y * rB.y + vb.z * rB.z + vb.w * rB.w);
#pragma unroll
        for (int off = 16; off > 0; off >>= 1)
            sum += __shfl_xor_sync(0xffffffff, sum, off);
        if (lane == 0) out[b * D + e] = sum;
    }
}

extern "C" void kernel_launch(void* const* d_in, const int* in_sizes, int n_in,
                              void* d_out, int out_size)
{
    const float* memory = (const float*)d_in[0];  // [B, D]
    const float* ctrl   = (const float*)d_in[1];  // [B, D]
    const float* kb     = (const float*)d_in[2];  // [B, D, S]
    const float* W      = (const float*)d_in[3];  // [D, D]
    // d_in[4] = b_concat: s-independent shift inside softmax -> drops out
    const float* w_attn = (const float*)d_in[5];  // [D]
    float* out = (float*)d_out;                   // [B, D]

    prep_kernel<<<dim3(4, 64), 256>>>(memory, ctrl, W, w_attn);
    logits_kernel<<<4 * BATCH, 256>>>(kb);
    readout_kernel<<<4 * BATCH, 256>>>(kb, out);
}